// round 16
// baseline (speedup 1.0000x reference)
#include <cuda_runtime.h>
#include <cuda_fp16.h>
#include <math.h>

#define BATCH 16
#define CH 64
#define HLO 80
#define WLO 80
#define HWLO (HLO*WLO)
#define HHI 160
#define WHI 160

// Scratch
__device__ __half g_zh[BATCH * HWLO * CH];  // conv(x), fp16, channel-last [b][hw][c]
__device__ float  g_om[BATCH * HWLO * 12];  // [b][hw][ ox(4), oy(4), sig(mask)(4) ]

__device__ __forceinline__ unsigned smem_u32(const void* p) {
    return (unsigned)__cvta_generic_to_shared(p);
}
__device__ __forceinline__ float tanh_approx(float x) {
    float r;
    asm("tanh.approx.f32 %0, %1;" : "=f"(r) : "f"(x));
    return r;
}

#define A_STRIDE 136   // halves per row (128 + 8 pad)
#define B_STRIDE 72    // halves per row (64 + 8 pad)
#define Z_STRIDE 72    // halves per px row in transpose buffer (64 + 8 pad)

// Dynamic smem layout (bytes). No Xf tile: offm reads x from gmem (L2-hot).
// Zs aliases As∪Bs (dead after mma reads; guarded by full __syncthreads).
#define SM_AS   0
#define SM_BS   (64 * A_STRIDE * 2)
#define SM_WO   (SM_BS + 64 * B_STRIDE * 2)
#define SM_PART (SM_WO + 64 * 12 * 4)
#define SM_TOTAL (SM_PART + 128 * 12 * 4)    // 35840

// ---------------------------------------------------------------------------
// Fused front kernel (R15-proven, unchanged).
// ---------------------------------------------------------------------------
__global__ __launch_bounds__(256) void front_kernel(
    const float* __restrict__ x,
    const float* __restrict__ conv_w,
    const float* __restrict__ offset_w,
    const float* __restrict__ offset_b,
    const float* __restrict__ mask_w,
    const float* __restrict__ mask_b)
{
    extern __shared__ char smem[];
    __half* As   = (__half*)(smem + SM_AS);
    __half* Bs   = (__half*)(smem + SM_BS);
    __half* Zs   = (__half*)(smem + SM_AS);   // alias As∪Bs, used post-mma
    float*  Wo   = (float*)(smem + SM_WO);
    float*  Part = (float*)(smem + SM_PART);

    const int b = blockIdx.y;
    const int pix0 = blockIdx.x * 128;
    const int t = threadIdx.x;

    const float* xb = x + ((size_t)b * CH) * HWLO + pix0;
    for (int idx = t; idx < 64 * 32; idx += 256) {
        int c = idx >> 5, p4 = (idx & 31) * 4;
        float4 v = *reinterpret_cast<const float4*>(&xb[c * HWLO + p4]);
        __half2 h0 = __floats2half2_rn(v.x, v.y);
        __half2 h1 = __floats2half2_rn(v.z, v.w);
        uint2 pk;
        pk.x = *reinterpret_cast<unsigned*>(&h0);
        pk.y = *reinterpret_cast<unsigned*>(&h1);
        *reinterpret_cast<uint2*>(&As[c * A_STRIDE + p4]) = pk;
    }
    for (int idx = t; idx < 64 * 16; idx += 256) {
        int o = idx >> 4, c4 = (idx & 15) * 4;
        float4 v = *reinterpret_cast<const float4*>(&conv_w[o * 64 + c4]);
        __half2 h0 = __floats2half2_rn(v.x, v.y);
        __half2 h1 = __floats2half2_rn(v.z, v.w);
        uint2 pk;
        pk.x = *reinterpret_cast<unsigned*>(&h0);
        pk.y = *reinterpret_cast<unsigned*>(&h1);
        *reinterpret_cast<uint2*>(&Bs[o * B_STRIDE + c4]) = pk;
    }
    for (int idx = t; idx < 64 * 12; idx += 256) {
        int c = idx / 12, o = idx % 12;
        Wo[c * 12 + o] = (o < 8) ? offset_w[o * 64 + c] : mask_w[(o - 8) * 64 + c];
    }
    __syncthreads();

    // ---- offm phase: x re-read from gmem (L2-hot), 2-way K split ----
    {
        const int px = t & 127;
        const int kh = t >> 7;
        float acc[12];
        #pragma unroll
        for (int o = 0; o < 12; o++) acc[o] = 0.f;

        const float* xcol = xb + (kh * 32) * HWLO + px;
        const float* wrow = &Wo[(kh * 32) * 12];
        #pragma unroll 8
        for (int c = 0; c < 32; c++) {
            float xv = xcol[c * HWLO];
            float4 w0 = *reinterpret_cast<const float4*>(&wrow[c * 12]);
            float4 w1 = *reinterpret_cast<const float4*>(&wrow[c * 12 + 4]);
            float4 w2 = *reinterpret_cast<const float4*>(&wrow[c * 12 + 8]);
            acc[0] += xv * w0.x;  acc[1] += xv * w0.y;
            acc[2] += xv * w0.z;  acc[3] += xv * w0.w;
            acc[4] += xv * w1.x;  acc[5] += xv * w1.y;
            acc[6] += xv * w1.z;  acc[7] += xv * w1.w;
            acc[8] += xv * w2.x;  acc[9] += xv * w2.y;
            acc[10] += xv * w2.z; acc[11] += xv * w2.w;
        }
        if (kh == 1) {
            #pragma unroll
            for (int o = 0; o < 12; o += 4)
                *reinterpret_cast<float4*>(&Part[px * 12 + o]) =
                    make_float4(acc[o], acc[o + 1], acc[o + 2], acc[o + 3]);
        }
        __syncthreads();
        if (kh == 0) {
            const size_t pxg = (size_t)b * HWLO + pix0 + px;
            float4 p0 = *reinterpret_cast<const float4*>(&Part[px * 12]);
            float4 p1 = *reinterpret_cast<const float4*>(&Part[px * 12 + 4]);
            float4 p2 = *reinterpret_cast<const float4*>(&Part[px * 12 + 8]);
            float4 st;
            st.x = acc[0] + p0.x + offset_b[0];
            st.y = acc[1] + p0.y + offset_b[1];
            st.z = acc[2] + p0.z + offset_b[2];
            st.w = acc[3] + p0.w + offset_b[3];
            *reinterpret_cast<float4*>(&g_om[pxg * 12]) = st;
            st.x = acc[4] + p1.x + offset_b[4];
            st.y = acc[5] + p1.y + offset_b[5];
            st.z = acc[6] + p1.z + offset_b[6];
            st.w = acc[7] + p1.w + offset_b[7];
            *reinterpret_cast<float4*>(&g_om[pxg * 12 + 4]) = st;
            st.x = __fdividef(1.f, 1.f + __expf(-(acc[8]  + p2.x + mask_b[0])));
            st.y = __fdividef(1.f, 1.f + __expf(-(acc[9]  + p2.y + mask_b[1])));
            st.z = __fdividef(1.f, 1.f + __expf(-(acc[10] + p2.z + mask_b[2])));
            st.w = __fdividef(1.f, 1.f + __expf(-(acc[11] + p2.w + mask_b[3])));
            *reinterpret_cast<float4*>(&g_om[pxg * 12 + 8]) = st;
        }
    }

    // ---- mma phase ----
    float d[8][4];
    {
        const int warp = t >> 5, lane = t & 31;
        int g = lane >> 3, r = lane & 7;
        int krow0 = ((g & 2) ? 8 : 0) + r;
        int pcol  = warp * 16 + ((g & 1) ? 8 : 0);
        unsigned a_base = smem_u32(&As[krow0 * A_STRIDE + pcol]);

        int rb = lane & 7;
        int kc = (lane & 8) ? 8 : 0;
        unsigned b_base = smem_u32(&Bs[rb * B_STRIDE + kc]);

        #pragma unroll
        for (int n = 0; n < 8; n++)
            #pragma unroll
            for (int i = 0; i < 4; i++) d[n][i] = 0.f;

        #pragma unroll
        for (int ks = 0; ks < 4; ks++) {
            unsigned a0, a1, a2, a3;
            asm volatile(
                "ldmatrix.sync.aligned.m8n8.x4.trans.shared.b16 {%0,%1,%2,%3}, [%4];"
                : "=r"(a0), "=r"(a1), "=r"(a2), "=r"(a3)
                : "r"(a_base + ks * (16 * A_STRIDE * 2)));
            #pragma unroll
            for (int n = 0; n < 8; n++) {
                unsigned b0, b1;
                asm volatile(
                    "ldmatrix.sync.aligned.m8n8.x2.shared.b16 {%0,%1}, [%2];"
                    : "=r"(b0), "=r"(b1)
                    : "r"(b_base + n * (8 * B_STRIDE * 2) + ks * 32));
                asm volatile(
                    "mma.sync.aligned.m16n8k16.row.col.f32.f16.f16.f32 "
                    "{%0,%1,%2,%3}, {%4,%5,%6,%7}, {%8,%9}, {%0,%1,%2,%3};"
                    : "+f"(d[n][0]), "+f"(d[n][1]), "+f"(d[n][2]), "+f"(d[n][3])
                    : "r"(a0), "r"(a1), "r"(a2), "r"(a3), "r"(b0), "r"(b1));
            }
        }
    }

    // ---- z epilogue: fragments -> smem transpose -> coalesced STG ----
    __syncthreads();
    {
        const int warp = t >> 5, lane = t & 31;
        const int row0 = warp * 16 + (lane >> 2);
        const int colp = (lane & 3) * 2;
        #pragma unroll
        for (int n = 0; n < 8; n++) {
            int ch = n * 8 + colp;
            __half2 h0 = __floats2half2_rn(d[n][0], d[n][1]);
            __half2 h1 = __floats2half2_rn(d[n][2], d[n][3]);
            *reinterpret_cast<__half2*>(&Zs[row0 * Z_STRIDE + ch])       = h0;
            *reinterpret_cast<__half2*>(&Zs[(row0 + 8) * Z_STRIDE + ch]) = h1;
        }
    }
    __syncthreads();
    {
        const size_t pxg0 = (size_t)b * HWLO + pix0;
        #pragma unroll
        for (int i = 0; i < 4; i++) {
            int idx = t + i * 256;
            int px = idx >> 3, chunk = (idx & 7) * 8;
            uint4 v = *reinterpret_cast<const uint4*>(&Zs[px * Z_STRIDE + chunk]);
            *reinterpret_cast<uint4*>(&g_zh[(pxg0 + px) * CH + chunk]) = v;
        }
    }
}

// ---------------------------------------------------------------------------
__device__ __forceinline__ void dim_weights(float coord, float w[3], int& rbase)
{
    w[0] = w[1] = w[2] = 0.f;
    int c0 = (int)floorf(coord);
    float f = coord - (float)c0;
    float cw0 = 1.f - f, cw1 = f;
    rbase = -1;
    #pragma unroll
    for (int k = 0; k < 2; k++) {
        int h = c0 + k;
        float cw = k ? cw1 : cw0;
        if (h < 0 || h >= HHI) continue;
        float cl = 0.5f * (float)h - 0.25f;
        cl = fminf(fmaxf(cl, 0.f), (float)(HLO - 1));
        int i0 = (int)cl;
        float fw = cl - (float)i0;
        int i1 = min(i0 + 1, HLO - 1);
        if (rbase < 0) rbase = i0;
        int d = i0 - rbase;
        w[d]             += cw * (1.f - fw);
        w[d + (i1 - i0)] += cw * fw;
    }
    if (rbase < 0) rbase = 0;
}

#define SOUT_STRIDE 40
__device__ __forceinline__ int sout_idx(int o, int px) {
    return o * SOUT_STRIDE + ((o >> 3) & 7) * 4 + px;
}

// ---------------------------------------------------------------------------
// Kernel 2: fused sampler v2 — 16 threads/px x 4 channels, 512-thread blocks.
// Per-thread state: 4 fp32 accs + 9 uint2 gathers (all batched, MLP=9).
// __launch_bounds__(512, 4): regs<=32 -> 64 warps/SM.
// Same lines per pixel as before (16 lanes x 8B = 128B = 1 line per tap).
// ---------------------------------------------------------------------------
__global__ __launch_bounds__(512, 4) void sample_kernel(
    float* __restrict__ out,
    const float* __restrict__ bn_gamma,
    const float* __restrict__ bn_beta,
    const float* __restrict__ bn_mean,
    const float* __restrict__ bn_var)
{
    __shared__ float2 s_row[32][3];
    __shared__ float2 s_col[32][3];
    __shared__ float  s_m[32];
    __shared__ float  s_bns[64];
    __shared__ float  s_bnb[64];
    __shared__ float  s_out[64 * SOUT_STRIDE + 64];

    const int t = threadIdx.x;
    const int b = blockIdx.z;
    const int hs = blockIdx.y;
    const int ws0 = blockIdx.x * 32;

    if (t < 64) {
        float sc = bn_gamma[t] * rsqrtf(bn_var[t] + 1e-5f);
        s_bns[t] = sc;
        s_bnb[t] = bn_beta[t] - bn_mean[t] * sc;
    }
    if (t < 32) {
        int ws = ws0 + t;
        int h = hs >> 1, w = ws >> 1;
        int p = ((hs & 1) << 1) | (ws & 1);
        const float* om = g_om + ((size_t)(b * HWLO + h * WLO + w) * 12);
        float ox = om[p];
        float oy = om[4 + p];
        s_m[t] = om[8 + p];
        float gx = -1.f + (float)ws * (2.f / (float)(WHI - 1)) + ox;
        float gy = -1.f + (float)hs * (2.f / (float)(HHI - 1)) + oy;
        float ix = ((gx + 1.f) * (float)WHI - 1.f) * 0.5f;
        float iy = ((gy + 1.f) * (float)HHI - 1.f) * 0.5f;
        float wy[3], wx[3]; int ry, rx;
        dim_weights(iy, wy, ry);
        dim_weights(ix, wx, rx);
        #pragma unroll
        for (int i = 0; i < 3; i++) {
            s_row[t][i] = make_float2(
                wy[i], __int_as_float(min(ry + i, HLO - 1) * (WLO * CH)));
            __half2 wh = __float2half2_rn(wx[i]);
            s_col[t][i] = make_float2(
                *reinterpret_cast<float*>(&wh),
                __int_as_float(min(rx + i, WLO - 1) * CH));
        }
    }
    __syncthreads();

    const int px = t >> 4;             // 0..31
    const int c0 = (t & 15) * 4;       // 4 channels per thread
    const __half* zb = g_zh + (size_t)b * HWLO * CH + c0;

    const float2 col0 = s_col[px][0];
    const float2 col1 = s_col[px][1];
    const float2 col2 = s_col[px][2];
    const __half2 w0 = *reinterpret_cast<const __half2*>(&col0.x);
    const __half2 w1 = *reinterpret_cast<const __half2*>(&col1.x);
    const __half2 w2 = *reinterpret_cast<const __half2*>(&col2.x);

    // Batch ALL 9 gathers up front (MLP = 9).
    uint2 v[3][3];
    #pragma unroll
    for (int i = 0; i < 3; i++) {
        const __half* base = zb + __float_as_int(s_row[px][i].y);
        v[i][0] = *reinterpret_cast<const uint2*>(base + __float_as_int(col0.y));
        v[i][1] = *reinterpret_cast<const uint2*>(base + __float_as_int(col1.y));
        v[i][2] = *reinterpret_cast<const uint2*>(base + __float_as_int(col2.y));
    }

    float acc[4] = {0.f, 0.f, 0.f, 0.f};
    #pragma unroll
    for (int i = 0; i < 3; i++) {
        __half2 s0 = __hmul2(*reinterpret_cast<const __half2*>(&v[i][0].x), w0);
        __half2 s1 = __hmul2(*reinterpret_cast<const __half2*>(&v[i][0].y), w0);
        s0 = __hfma2(*reinterpret_cast<const __half2*>(&v[i][1].x), w1, s0);
        s1 = __hfma2(*reinterpret_cast<const __half2*>(&v[i][1].y), w1, s1);
        s0 = __hfma2(*reinterpret_cast<const __half2*>(&v[i][2].x), w2, s0);
        s1 = __hfma2(*reinterpret_cast<const __half2*>(&v[i][2].y), w2, s1);

        float wyi = s_row[px][i].x;
        float2 f0 = __half22float2(s0);
        float2 f1 = __half22float2(s1);
        acc[0] = fmaf(wyi, f0.x, acc[0]);
        acc[1] = fmaf(wyi, f0.y, acc[1]);
        acc[2] = fmaf(wyi, f1.x, acc[2]);
        acc[3] = fmaf(wyi, f1.y, acc[3]);
    }

    const float m = s_m[px];
    #pragma unroll
    for (int j = 0; j < 4; j++) {
        int o = c0 + j;
        float y = acc[j] * (m * s_bns[o]) + s_bnb[o];
        float hf = 0.5f * y;
        s_out[sout_idx(o, px)] = fmaf(hf, tanh_approx(hf), hf);   // SiLU
    }
    __syncthreads();

    // Coalesced NCHW writes: 512 threads x 1 float4 = 2048 floats
    {
        int o = t >> 3, px0 = (t & 7) * 4;
        const float* src = &s_out[sout_idx(o, px0)];
        float4 vv = *reinterpret_cast<const float4*>(src);
        *reinterpret_cast<float4*>(
            out + (((size_t)(b * CH + o)) * HHI + hs) * WHI + ws0 + px0) = vv;
    }
}

// ---------------------------------------------------------------------------
extern "C" void kernel_launch(void* const* d_in, const int* in_sizes, int n_in,
                              void* d_out, int out_size)
{
    const float* x        = (const float*)d_in[0];
    const float* offset_w = (const float*)d_in[1];
    const float* offset_b = (const float*)d_in[2];
    const float* mask_w   = (const float*)d_in[3];
    const float* mask_b   = (const float*)d_in[4];
    const float* conv_w   = (const float*)d_in[5];
    const float* bn_gamma = (const float*)d_in[6];
    const float* bn_beta  = (const float*)d_in[7];
    const float* bn_mean  = (const float*)d_in[8];
    const float* bn_var   = (const float*)d_in[9];
    float* out = (float*)d_out;

    cudaFuncSetAttribute(front_kernel,
                         cudaFuncAttributeMaxDynamicSharedMemorySize, SM_TOTAL);

    front_kernel<<<dim3(HWLO / 128, BATCH), 256, SM_TOTAL>>>(
        x, conv_w, offset_w, offset_b, mask_w, mask_b);
    sample_kernel<<<dim3(WHI / 32, HHI, BATCH), 512>>>(
        out, bn_gamma, bn_beta, bn_mean, bn_var);
}

// round 17
// speedup vs baseline: 1.2364x; 1.2364x over previous
#include <cuda_runtime.h>
#include <cuda_fp16.h>
#include <math.h>

#define BATCH 16
#define CH 64
#define HLO 80
#define WLO 80
#define HWLO (HLO*WLO)
#define HHI 160
#define WHI 160

// Scratch
__device__ __half g_zh[BATCH * HWLO * CH];  // conv(x), fp16, channel-last [b][hw][c]
__device__ float  g_om[BATCH * HWLO * 12];  // [b][hw][ ox(4), oy(4), sig(mask)(4) ]

__device__ __forceinline__ unsigned smem_u32(const void* p) {
    return (unsigned)__cvta_generic_to_shared(p);
}
__device__ __forceinline__ float tanh_approx(float x) {
    float r;
    asm("tanh.approx.f32 %0, %1;" : "=f"(r) : "f"(x));
    return r;
}

#define A_STRIDE 136   // halves per row (128 + 8 pad)
#define B_STRIDE 72    // halves per row (64 + 8 pad)
#define Z_STRIDE 72    // halves per px row in transpose buffer (64 + 8 pad)

// Dynamic smem layout (bytes). Zs aliases As∪Bs (dead after mma reads).
#define SM_AS   0
#define SM_BS   (64 * A_STRIDE * 2)
#define SM_WO   (SM_BS + 64 * B_STRIDE * 2)
#define SM_PART (SM_WO + 64 * 12 * 4)
#define SM_TOTAL (SM_PART + 128 * 12 * 4)    // 35840

// ---------------------------------------------------------------------------
// Fused front kernel v2: SINGLE pass over x.
// Thread (px, kh) streams x[kh*32+c][px] once: converts+stores into As AND
// accumulates the 12 offm outputs in registers (no second read of x).
//  - offsets+mask fp32, 2-way K-split, smem combine (numerics = R15)
//  - z = conv_w @ x via m16n8k16 tensor cores
//  - z epilogue: smem transpose -> coalesced 16B stores
// ---------------------------------------------------------------------------
__global__ __launch_bounds__(256) void front_kernel(
    const float* __restrict__ x,
    const float* __restrict__ conv_w,
    const float* __restrict__ offset_w,
    const float* __restrict__ offset_b,
    const float* __restrict__ mask_w,
    const float* __restrict__ mask_b)
{
    extern __shared__ char smem[];
    __half* As   = (__half*)(smem + SM_AS);
    __half* Bs   = (__half*)(smem + SM_BS);
    __half* Zs   = (__half*)(smem + SM_AS);   // alias As∪Bs, used post-mma
    float*  Wo   = (float*)(smem + SM_WO);
    float*  Part = (float*)(smem + SM_PART);

    const int b = blockIdx.y;
    const int pix0 = blockIdx.x * 128;
    const int t = threadIdx.x;

    // ---- phase 0: weights into smem ----
    for (int idx = t; idx < 64 * 16; idx += 256) {
        int o = idx >> 4, c4 = (idx & 15) * 4;
        float4 v = *reinterpret_cast<const float4*>(&conv_w[o * 64 + c4]);
        __half2 h0 = __floats2half2_rn(v.x, v.y);
        __half2 h1 = __floats2half2_rn(v.z, v.w);
        uint2 pk;
        pk.x = *reinterpret_cast<unsigned*>(&h0);
        pk.y = *reinterpret_cast<unsigned*>(&h1);
        *reinterpret_cast<uint2*>(&Bs[o * B_STRIDE + c4]) = pk;
    }
    for (int idx = t; idx < 64 * 12; idx += 256) {
        int c = idx / 12, o = idx % 12;
        Wo[c * 12 + o] = (o < 8) ? offset_w[o * 64 + c] : mask_w[(o - 8) * 64 + c];
    }
    __syncthreads();

    // ---- phase 1: merged x stream: LDG -> (STS to As) + (offm FMA) ----
    const int px = t & 127;
    const int kh = t >> 7;
    {
        float acc[12];
        #pragma unroll
        for (int o = 0; o < 12; o++) acc[o] = 0.f;

        const float* xcol = x + ((size_t)b * CH + kh * 32) * HWLO + pix0 + px;
        const float* wrow = &Wo[(kh * 32) * 12];
        __half* arow = &As[(kh * 32) * A_STRIDE + px];
        #pragma unroll 8
        for (int c = 0; c < 32; c++) {
            float xv = xcol[c * HWLO];
            arow[c * A_STRIDE] = __float2half_rn(xv);
            float4 w0 = *reinterpret_cast<const float4*>(&wrow[c * 12]);
            float4 w1 = *reinterpret_cast<const float4*>(&wrow[c * 12 + 4]);
            float4 w2 = *reinterpret_cast<const float4*>(&wrow[c * 12 + 8]);
            acc[0] += xv * w0.x;  acc[1] += xv * w0.y;
            acc[2] += xv * w0.z;  acc[3] += xv * w0.w;
            acc[4] += xv * w1.x;  acc[5] += xv * w1.y;
            acc[6] += xv * w1.z;  acc[7] += xv * w1.w;
            acc[8] += xv * w2.x;  acc[9] += xv * w2.y;
            acc[10] += xv * w2.z; acc[11] += xv * w2.w;
        }
        if (kh == 1) {
            #pragma unroll
            for (int o = 0; o < 12; o += 4)
                *reinterpret_cast<float4*>(&Part[px * 12 + o]) =
                    make_float4(acc[o], acc[o + 1], acc[o + 2], acc[o + 3]);
        }
        __syncthreads();   // As complete (for mma) + Part visible
        if (kh == 0) {
            const size_t pxg = (size_t)b * HWLO + pix0 + px;
            float4 p0 = *reinterpret_cast<const float4*>(&Part[px * 12]);
            float4 p1 = *reinterpret_cast<const float4*>(&Part[px * 12 + 4]);
            float4 p2 = *reinterpret_cast<const float4*>(&Part[px * 12 + 8]);
            float4 st;
            st.x = acc[0] + p0.x + offset_b[0];
            st.y = acc[1] + p0.y + offset_b[1];
            st.z = acc[2] + p0.z + offset_b[2];
            st.w = acc[3] + p0.w + offset_b[3];
            *reinterpret_cast<float4*>(&g_om[pxg * 12]) = st;
            st.x = acc[4] + p1.x + offset_b[4];
            st.y = acc[5] + p1.y + offset_b[5];
            st.z = acc[6] + p1.z + offset_b[6];
            st.w = acc[7] + p1.w + offset_b[7];
            *reinterpret_cast<float4*>(&g_om[pxg * 12 + 4]) = st;
            st.x = __fdividef(1.f, 1.f + __expf(-(acc[8]  + p2.x + mask_b[0])));
            st.y = __fdividef(1.f, 1.f + __expf(-(acc[9]  + p2.y + mask_b[1])));
            st.z = __fdividef(1.f, 1.f + __expf(-(acc[10] + p2.z + mask_b[2])));
            st.w = __fdividef(1.f, 1.f + __expf(-(acc[11] + p2.w + mask_b[3])));
            *reinterpret_cast<float4*>(&g_om[pxg * 12 + 8]) = st;
        }
    }

    // ---- mma phase ----
    float d[8][4];
    {
        const int warp = t >> 5, lane = t & 31;
        int g = lane >> 3, r = lane & 7;
        int krow0 = ((g & 2) ? 8 : 0) + r;
        int pcol  = warp * 16 + ((g & 1) ? 8 : 0);
        unsigned a_base = smem_u32(&As[krow0 * A_STRIDE + pcol]);

        int rb = lane & 7;
        int kc = (lane & 8) ? 8 : 0;
        unsigned b_base = smem_u32(&Bs[rb * B_STRIDE + kc]);

        #pragma unroll
        for (int n = 0; n < 8; n++)
            #pragma unroll
            for (int i = 0; i < 4; i++) d[n][i] = 0.f;

        #pragma unroll
        for (int ks = 0; ks < 4; ks++) {
            unsigned a0, a1, a2, a3;
            asm volatile(
                "ldmatrix.sync.aligned.m8n8.x4.trans.shared.b16 {%0,%1,%2,%3}, [%4];"
                : "=r"(a0), "=r"(a1), "=r"(a2), "=r"(a3)
                : "r"(a_base + ks * (16 * A_STRIDE * 2)));
            #pragma unroll
            for (int n = 0; n < 8; n++) {
                unsigned b0, b1;
                asm volatile(
                    "ldmatrix.sync.aligned.m8n8.x2.shared.b16 {%0,%1}, [%2];"
                    : "=r"(b0), "=r"(b1)
                    : "r"(b_base + n * (8 * B_STRIDE * 2) + ks * 32));
                asm volatile(
                    "mma.sync.aligned.m16n8k16.row.col.f32.f16.f16.f32 "
                    "{%0,%1,%2,%3}, {%4,%5,%6,%7}, {%8,%9}, {%0,%1,%2,%3};"
                    : "+f"(d[n][0]), "+f"(d[n][1]), "+f"(d[n][2]), "+f"(d[n][3])
                    : "r"(a0), "r"(a1), "r"(a2), "r"(a3), "r"(b0), "r"(b1));
            }
        }
    }

    // ---- z epilogue: fragments -> smem transpose -> coalesced STG ----
    __syncthreads();   // all ldmatrix As/Bs reads complete
    {
        const int warp = t >> 5, lane = t & 31;
        const int row0 = warp * 16 + (lane >> 2);
        const int colp = (lane & 3) * 2;
        #pragma unroll
        for (int n = 0; n < 8; n++) {
            int ch = n * 8 + colp;
            __half2 h0 = __floats2half2_rn(d[n][0], d[n][1]);
            __half2 h1 = __floats2half2_rn(d[n][2], d[n][3]);
            *reinterpret_cast<__half2*>(&Zs[row0 * Z_STRIDE + ch])       = h0;
            *reinterpret_cast<__half2*>(&Zs[(row0 + 8) * Z_STRIDE + ch]) = h1;
        }
    }
    __syncthreads();
    {
        const size_t pxg0 = (size_t)b * HWLO + pix0;
        #pragma unroll
        for (int i = 0; i < 4; i++) {
            int idx = t + i * 256;
            int p2 = idx >> 3, chunk = (idx & 7) * 8;
            uint4 v = *reinterpret_cast<const uint4*>(&Zs[p2 * Z_STRIDE + chunk]);
            *reinterpret_cast<uint4*>(&g_zh[(pxg0 + p2) * CH + chunk]) = v;
        }
    }
}

// ---------------------------------------------------------------------------
__device__ __forceinline__ void dim_weights(float coord, float w[3], int& rbase)
{
    w[0] = w[1] = w[2] = 0.f;
    int c0 = (int)floorf(coord);
    float f = coord - (float)c0;
    float cw0 = 1.f - f, cw1 = f;
    rbase = -1;
    #pragma unroll
    for (int k = 0; k < 2; k++) {
        int h = c0 + k;
        float cw = k ? cw1 : cw0;
        if (h < 0 || h >= HHI) continue;
        float cl = 0.5f * (float)h - 0.25f;
        cl = fminf(fmaxf(cl, 0.f), (float)(HLO - 1));
        int i0 = (int)cl;
        float fw = cl - (float)i0;
        int i1 = min(i0 + 1, HLO - 1);
        if (rbase < 0) rbase = i0;
        int d = i0 - rbase;
        w[d]             += cw * (1.f - fw);
        w[d + (i1 - i0)] += cw * fw;
    }
    if (rbase < 0) rbase = 0;
}

#define SOUT_STRIDE 40
__device__ __forceinline__ int sout_idx(int o, int px) {
    return o * SOUT_STRIDE + ((o >> 3) & 7) * 4 + px;
}

// ---------------------------------------------------------------------------
// Kernel 2: fused sampler — EXACT R12 configuration (frozen; best: 55.2us).
// ---------------------------------------------------------------------------
__global__ __launch_bounds__(256) void sample_kernel(
    float* __restrict__ out,
    const float* __restrict__ bn_gamma,
    const float* __restrict__ bn_beta,
    const float* __restrict__ bn_mean,
    const float* __restrict__ bn_var)
{
    __shared__ float2 s_row[32][3];
    __shared__ float2 s_col[32][3];
    __shared__ float  s_m[32];
    __shared__ float  s_bns[64];
    __shared__ float  s_bnb[64];
    __shared__ float  s_out[64 * SOUT_STRIDE + 64];

    const int t = threadIdx.x;
    const int b = blockIdx.z;
    const int hs = blockIdx.y;
    const int ws0 = blockIdx.x * 32;

    if (t < 64) {
        float sc = bn_gamma[t] * rsqrtf(bn_var[t] + 1e-5f);
        s_bns[t] = sc;
        s_bnb[t] = bn_beta[t] - bn_mean[t] * sc;
    }
    if (t < 32) {
        int ws = ws0 + t;
        int h = hs >> 1, w = ws >> 1;
        int p = ((hs & 1) << 1) | (ws & 1);
        const float* om = g_om + ((size_t)(b * HWLO + h * WLO + w) * 12);
        float ox = om[p];
        float oy = om[4 + p];
        s_m[t] = om[8 + p];
        float gx = -1.f + (float)ws * (2.f / (float)(WHI - 1)) + ox;
        float gy = -1.f + (float)hs * (2.f / (float)(HHI - 1)) + oy;
        float ix = ((gx + 1.f) * (float)WHI - 1.f) * 0.5f;
        float iy = ((gy + 1.f) * (float)HHI - 1.f) * 0.5f;
        float wy[3], wx[3]; int ry, rx;
        dim_weights(iy, wy, ry);
        dim_weights(ix, wx, rx);
        #pragma unroll
        for (int i = 0; i < 3; i++) {
            s_row[t][i] = make_float2(
                wy[i], __int_as_float(min(ry + i, HLO - 1) * (WLO * CH)));
            __half2 wh = __float2half2_rn(wx[i]);
            s_col[t][i] = make_float2(
                *reinterpret_cast<float*>(&wh),
                __int_as_float(min(rx + i, WLO - 1) * CH));
        }
    }
    __syncthreads();

    const int px = t >> 3;
    const int c0 = (t & 7) * 8;
    const __half* zb = g_zh + (size_t)b * HWLO * CH + c0;

    const float2 col0 = s_col[px][0];
    const float2 col1 = s_col[px][1];
    const float2 col2 = s_col[px][2];
    const __half2 w0 = *reinterpret_cast<const __half2*>(&col0.x);
    const __half2 w1 = *reinterpret_cast<const __half2*>(&col1.x);
    const __half2 w2 = *reinterpret_cast<const __half2*>(&col2.x);

    float acc[8];
    #pragma unroll
    for (int j = 0; j < 8; j++) acc[j] = 0.f;

    #pragma unroll
    for (int i = 0; i < 3; i++) {
        float2 rt = s_row[px][i];
        const __half* base = zb + __float_as_int(rt.y);
        uint4 v0 = *reinterpret_cast<const uint4*>(base + __float_as_int(col0.y));
        uint4 v1 = *reinterpret_cast<const uint4*>(base + __float_as_int(col1.y));
        uint4 v2 = *reinterpret_cast<const uint4*>(base + __float_as_int(col2.y));

        __half2 s0 = __hmul2(*reinterpret_cast<const __half2*>(&v0.x), w0);
        __half2 s1 = __hmul2(*reinterpret_cast<const __half2*>(&v0.y), w0);
        __half2 s2 = __hmul2(*reinterpret_cast<const __half2*>(&v0.z), w0);
        __half2 s3 = __hmul2(*reinterpret_cast<const __half2*>(&v0.w), w0);
        s0 = __hfma2(*reinterpret_cast<const __half2*>(&v1.x), w1, s0);
        s1 = __hfma2(*reinterpret_cast<const __half2*>(&v1.y), w1, s1);
        s2 = __hfma2(*reinterpret_cast<const __half2*>(&v1.z), w1, s2);
        s3 = __hfma2(*reinterpret_cast<const __half2*>(&v1.w), w1, s3);
        s0 = __hfma2(*reinterpret_cast<const __half2*>(&v2.x), w2, s0);
        s1 = __hfma2(*reinterpret_cast<const __half2*>(&v2.y), w2, s1);
        s2 = __hfma2(*reinterpret_cast<const __half2*>(&v2.z), w2, s2);
        s3 = __hfma2(*reinterpret_cast<const __half2*>(&v2.w), w2, s3);

        float wyi = rt.x;
        float2 f0 = __half22float2(s0);
        float2 f1 = __half22float2(s1);
        float2 f2 = __half22float2(s2);
        float2 f3 = __half22float2(s3);
        acc[0] = fmaf(wyi, f0.x, acc[0]);
        acc[1] = fmaf(wyi, f0.y, acc[1]);
        acc[2] = fmaf(wyi, f1.x, acc[2]);
        acc[3] = fmaf(wyi, f1.y, acc[3]);
        acc[4] = fmaf(wyi, f2.x, acc[4]);
        acc[5] = fmaf(wyi, f2.y, acc[5]);
        acc[6] = fmaf(wyi, f3.x, acc[6]);
        acc[7] = fmaf(wyi, f3.y, acc[7]);
    }

    const float m = s_m[px];
    #pragma unroll
    for (int j = 0; j < 8; j++) {
        int o = c0 + j;
        float y = acc[j] * (m * s_bns[o]) + s_bnb[o];
        float hf = 0.5f * y;
        s_out[sout_idx(o, px)] = fmaf(hf, tanh_approx(hf), hf);   // SiLU
    }
    __syncthreads();

    #pragma unroll
    for (int r = 0; r < 2; r++) {
        int idx = t + r * 256;
        int o = idx >> 3, px0 = (idx & 7) * 4;
        const float* src = &s_out[sout_idx(o, px0)];
        float4 v = *reinterpret_cast<const float4*>(src);
        *reinterpret_cast<float4*>(
            out + (((size_t)(b * CH + o)) * HHI + hs) * WHI + ws0 + px0) = v;
    }
}

// ---------------------------------------------------------------------------
extern "C" void kernel_launch(void* const* d_in, const int* in_sizes, int n_in,
                              void* d_out, int out_size)
{
    const float* x        = (const float*)d_in[0];
    const float* offset_w = (const float*)d_in[1];
    const float* offset_b = (const float*)d_in[2];
    const float* mask_w   = (const float*)d_in[3];
    const float* mask_b   = (const float*)d_in[4];
    const float* conv_w   = (const float*)d_in[5];
    const float* bn_gamma = (const float*)d_in[6];
    const float* bn_beta  = (const float*)d_in[7];
    const float* bn_mean  = (const float*)d_in[8];
    const float* bn_var   = (const float*)d_in[9];
    float* out = (float*)d_out;

    cudaFuncSetAttribute(front_kernel,
                         cudaFuncAttributeMaxDynamicSharedMemorySize, SM_TOTAL);

    front_kernel<<<dim3(HWLO / 128, BATCH), 256, SM_TOTAL>>>(
        x, conv_w, offset_w, offset_b, mask_w, mask_b);
    sample_kernel<<<dim3(WHI / 32, HHI, BATCH), 256>>>(
        out, bn_gamma, bn_beta, bn_mean, bn_var);
}